// round 3
// baseline (speedup 1.0000x reference)
#include <cuda_runtime.h>
#include <math.h>

#define HH 256
#define WW 512
#define HW (HH*WW)            // 131072
#define NPB (HW*2)            // 262144 boxes per branch
#define NTOT (NPB*2)          // 524288 total
#define TOPK 4096
#define SCORE_THR 0.2f
#define NMS_THR 0.15f
#define NBUCKET 65536
#define MAXCAND 8192

// ---------------- scratch (static device globals; no allocations) ----------------
__device__ float               g_scores[NTOT];
__device__ unsigned int        g_hist[NBUCKET];
__device__ int                 g_cut;
__device__ unsigned long long  g_cand[MAXCAND];
__device__ int                 g_cand_count;
__device__ float               g_topk_val[TOPK];
__device__ int                 g_topk_idx[TOPK];
__device__ float4              g_standup[TOPK];
__device__ unsigned long long  g_mask[TOPK * 64];   // 2MB suppression bitmask
__device__ unsigned long long  g_any[64];           // per-row "has any suppression bit"
__device__ unsigned long long  g_remv[64];          // final removed bitmask

// ---------------- K0: zero scratch ----------------
__global__ void k_init() {
    int i = blockIdx.x * blockDim.x + threadIdx.x;
    if (i < NBUCKET) g_hist[i] = 0u;
    if (i < 64)      g_any[i] = 0ull;
    if (i == 0)      g_cand_count = 0;
}

// ---------------- K1: sigmoid scores + bucket histogram ----------------
__global__ void k_scores(const float* __restrict__ psm_v, const float* __restrict__ psm_i) {
    int n = blockIdx.x * blockDim.x + threadIdx.x;
    if (n >= NTOT) return;
    int br = (n >= NPB);
    int m = br ? (n - NPB) : n;
    int cell = m >> 1, a = m & 1;
    float x = (br ? psm_i : psm_v)[a * HW + cell];
    // match XLA logistic expansion: 1 / (1 + exp(-x))
    float s = 1.0f / (1.0f + expf(-x));
    g_scores[n] = s;
    if (s > SCORE_THR) {
        unsigned int b = __float_as_uint(s) >> 16;   // positive floats: bits order = value order
        atomicAdd(&g_hist[b], 1u);
    }
}

// ---------------- K2: find cut bucket (single block) ----------------
__global__ void k_findcut() {
    __shared__ unsigned int csum[256];
    int t = threadIdx.x;
    unsigned int sum = 0;
    int base = t * 256;
    for (int i = 0; i < 256; i++) sum += g_hist[base + i];
    csum[t] = sum;
    __syncthreads();
    if (t == 0) {
        unsigned int cum = 0;
        int c = 255;
        for (; c >= 0; c--) {
            if (cum + csum[c] >= TOPK) break;
            cum += csum[c];
        }
        if (c < 0) { g_cut = 0; return; }
        int b = c * 256 + 255;
        for (; b >= c * 256; b--) {
            cum += g_hist[b];
            if (cum >= TOPK) break;
        }
        if (b < c * 256) b = c * 256;
        g_cut = b;
    }
}

// ---------------- K3: compact candidates >= cut bucket ----------------
__global__ void k_compact() {
    int n = blockIdx.x * blockDim.x + threadIdx.x;
    if (n >= NTOT) return;
    float s = g_scores[n];
    if (s > SCORE_THR) {
        unsigned int bits = __float_as_uint(s);
        if ((int)(bits >> 16) >= g_cut) {
            int p = atomicAdd(&g_cand_count, 1);
            if (p < MAXCAND) {
                // key: value desc, index asc (via complement) when sorted ascending and read from top
                g_cand[p] = ((unsigned long long)bits << 32)
                          | (unsigned long long)(0xFFFFFFFFu - (unsigned int)n);
            }
        }
    }
}

// ---------------- K4: one-block bitonic sort of candidates, emit top 4096 ----------------
__global__ void k_sort() {
    extern __shared__ unsigned long long sk[];
    int t = threadIdx.x;
    int cnt = g_cand_count;
    if (cnt > MAXCAND) cnt = MAXCAND;
    for (int i = t; i < MAXCAND; i += blockDim.x)
        sk[i] = (i < cnt) ? g_cand[i] : 0ull;
    __syncthreads();
    for (int k = 2; k <= MAXCAND; k <<= 1) {
        for (int j = k >> 1; j > 0; j >>= 1) {
            for (int i = t; i < MAXCAND; i += blockDim.x) {
                int l = i ^ j;
                if (l > i) {
                    unsigned long long a = sk[i], b = sk[l];
                    bool up = ((i & k) == 0);
                    if (up ? (a > b) : (a < b)) { sk[i] = b; sk[l] = a; }
                }
            }
            __syncthreads();
        }
    }
    // ascending order -> rank r is element MAXCAND-1-r
    for (int r = t; r < TOPK; r += blockDim.x) {
        unsigned long long key = sk[MAXCAND - 1 - r];
        unsigned int bits = (unsigned int)(key >> 32);
        unsigned int n = 0xFFFFFFFFu - (unsigned int)(key & 0xFFFFFFFFull);
        if (key == 0ull) { bits = 0u; n = 0u; }   // pad safety
        g_topk_val[r] = __uint_as_float(bits);
        g_topk_idx[r] = (int)n;
    }
}

// ---------------- geometry helpers ----------------
__device__ __forceinline__ void make_corners(const float* b, float* cx, float* cy, float* cz) {
    const float sx[8] = { 0.5f, 0.5f,-0.5f,-0.5f, 0.5f, 0.5f,-0.5f,-0.5f};
    const float sy[8] = { 0.5f,-0.5f,-0.5f, 0.5f, 0.5f,-0.5f,-0.5f, 0.5f};
    const float sz[8] = {-0.5f,-0.5f,-0.5f,-0.5f, 0.5f, 0.5f, 0.5f, 0.5f};
    float c = cosf(b[6]), s = sinf(b[6]);
#pragma unroll
    for (int k = 0; k < 8; k++) {
        float x = b[5] * sx[k];   // l
        float y = b[4] * sy[k];   // w
        float z = b[3] * sz[k];   // h
        cx[k] = x * c - y * s + b[0];
        cy[k] = x * s + y * c + b[1];
        cz[k] = z + b[2];
    }
}

__device__ __forceinline__ void apply_T(const float* __restrict__ T,
                                        float* cx, float* cy, float* cz) {
    float T00 = T[0], T01 = T[1], T02 = T[2],  T03 = T[3];
    float T10 = T[4], T11 = T[5], T12 = T[6],  T13 = T[7];
    float T20 = T[8], T21 = T[9], T22 = T[10], T23 = T[11];
#pragma unroll
    for (int k = 0; k < 8; k++) {
        float x = cx[k], y = cy[k], z = cz[k];
        cx[k] = T00 * x + T01 * y + T02 * z + T03;
        cy[k] = T10 * x + T11 * y + T12 * z + T13;
        cz[k] = T20 * x + T21 * y + T22 * z + T23;
    }
}

__device__ __forceinline__ void corner_to_center(const float* cx, const float* cy,
                                                 const float* cz, float* b) {
    float mx = 0.f, my = 0.f, mz = 0.f;
#pragma unroll
    for (int k = 0; k < 8; k++) { mx += cx[k]; my += cy[k]; mz += cz[k]; }
    mx *= 0.125f; my *= 0.125f; mz *= 0.125f;
    float h = (cz[4] + cz[5] + cz[6] + cz[7]) * 0.25f
            - (cz[0] + cz[1] + cz[2] + cz[3]) * 0.25f;
    const int li[4] = {0, 1, 4, 5}, lj[4] = {3, 2, 7, 6};
    const int wi[4] = {0, 3, 4, 7}, wj[4] = {1, 2, 5, 6};
    float l = 0.f, w = 0.f, sdx = 0.f, sdy = 0.f;
#pragma unroll
    for (int k = 0; k < 4; k++) {
        float dx = cx[li[k]] - cx[lj[k]];
        float dy = cy[li[k]] - cy[lj[k]];
        l += sqrtf(dx * dx + dy * dy);
        sdx += dx; sdy += dy;
    }
    l *= 0.25f;
#pragma unroll
    for (int k = 0; k < 4; k++) {
        float dx = cx[wi[k]] - cx[wj[k]];
        float dy = cy[wi[k]] - cy[wj[k]];
        w += sqrtf(dx * dx + dy * dy);
    }
    w *= 0.25f;
    float yaw = atan2f(sdy, sdx);
    b[0] = mx; b[1] = my; b[2] = mz; b[3] = h; b[4] = w; b[5] = l; b[6] = yaw;
}

// ---------------- K5: decode selected boxes -> corners (out cols 0..23) + standup ----------------
__global__ void k_decode(const float* __restrict__ anchors,
                         const float* __restrict__ rm_v,
                         const float* __restrict__ rm_i,
                         const float* __restrict__ t_proj,
                         const float* __restrict__ t_ego,
                         float* __restrict__ out) {
    int r = blockIdx.x * blockDim.x + threadIdx.x;
    if (r >= TOPK) return;
    int n = g_topk_idx[r];
    int br = (n >= NPB);
    int m = br ? (n - NPB) : n;
    const float* rm = br ? rm_i : rm_v;
    int cell = m >> 1, a = m & 1;
    const float* anc = anchors + (size_t)m * 7;

    float d[7];
#pragma unroll
    for (int j = 0; j < 7; j++) d[j] = rm[(a * 7 + j) * HW + cell];

    float a0 = anc[0], a1 = anc[1], a2 = anc[2], a3 = anc[3];
    float a4 = anc[4], a5 = anc[5], a6 = anc[6];
    float ad = sqrtf(a4 * a4 + a5 * a5);

    float b[7];
    b[0] = d[0] * ad + a0;
    b[1] = d[1] * ad + a1;
    b[2] = d[2] * a3 + a2;
    b[3] = expf(d[3]) * a3;
    b[4] = expf(d[4]) * a4;
    b[5] = expf(d[5]) * a5;
    b[6] = d[6] + a6;

    float cx[8], cy[8], cz[8];
    make_corners(b, cx, cy, cz);
    if (br) {
        apply_T(t_proj, cx, cy, cz);
        corner_to_center(cx, cy, cz, b);
        make_corners(b, cx, cy, cz);
    }
    apply_T(t_ego, cx, cy, cz);

    float mnx = cx[0], mny = cy[0], mxx = cx[0], mxy = cy[0];
    float* o = out + (size_t)r * 25;
#pragma unroll
    for (int k = 0; k < 8; k++) {
        o[k * 3 + 0] = cx[k];
        o[k * 3 + 1] = cy[k];
        o[k * 3 + 2] = cz[k];
        mnx = fminf(mnx, cx[k]); mny = fminf(mny, cy[k]);
        mxx = fmaxf(mxx, cx[k]); mxy = fmaxf(mxy, cy[k]);
    }
    g_standup[r] = make_float4(mnx, mny, mxx, mxy);
}

// ---------------- K6: suppression bitmask matrix ----------------
__global__ void k_mask() {
    __shared__ float4 cb[64];
    int t = threadIdx.x;                 // 64 threads
    int col0 = blockIdx.x * 64;
    cb[t] = g_standup[col0 + t];
    __syncthreads();
    int row = blockIdx.y * 64 + t;
    float4 rb = g_standup[row];
    float rArea = (rb.z - rb.x) * (rb.w - rb.y);
    unsigned long long bits = 0ull;
#pragma unroll 4
    for (int j = 0; j < 64; j++) {
        int col = col0 + j;
        if (col > row) {
            float4 c = cb[j];
            float lx = fmaxf(rb.x, c.x), ly = fmaxf(rb.y, c.y);
            float rx = fminf(rb.z, c.z), ry = fminf(rb.w, c.w);
            float w = fmaxf(rx - lx, 0.f), h = fmaxf(ry - ly, 0.f);
            float inter = w * h;
            float cArea = (c.z - c.x) * (c.w - c.y);
            float iou = inter / (rArea + cArea - inter + 1e-6f);
            if (iou > NMS_THR) bits |= (1ull << j);
        }
    }
    g_mask[(size_t)row * 64 + blockIdx.x] = bits;
    if (bits) atomicOr(&g_any[row >> 6], 1ull << (row & 63));
}

// ---------------- K7: serial greedy scan (single warp), skipping no-op rows ----------------
__global__ void k_nms() {
    int lane = threadIdx.x;              // 32 threads; lane owns words 2*lane, 2*lane+1
    __shared__ unsigned long long sAny[64];
    __shared__ short sActive[TOPK];
    __shared__ int sCount;
    sAny[2 * lane]     = g_any[2 * lane];
    sAny[2 * lane + 1] = g_any[2 * lane + 1];

    // init removed = !valid
    unsigned long long r0 = 0ull, r1 = 0ull;
    for (int bb = 0; bb < 64; bb++) {
        if (!(g_topk_val[(2 * lane) * 64 + bb]     > SCORE_THR)) r0 |= (1ull << bb);
        if (!(g_topk_val[(2 * lane + 1) * 64 + bb] > SCORE_THR)) r1 |= (1ull << bb);
    }
    __syncwarp();
    if (lane == 0) {
        int c = 0;
        for (int w = 0; w < 64; w++) {
            unsigned long long aw = sAny[w];
            while (aw) {
                int bb = __ffsll((long long)aw) - 1;
                aw &= aw - 1;
                sActive[c++] = (short)(w * 64 + bb);
            }
        }
        sCount = c;
    }
    __syncwarp();
    int cnt = sCount;

    unsigned long long m0 = 0ull, m1 = 0ull;
    if (cnt > 0) {
        int row = sActive[0];
        m0 = g_mask[(size_t)row * 64 + 2 * lane];
        m1 = g_mask[(size_t)row * 64 + 2 * lane + 1];
    }
    for (int t = 0; t < cnt; t++) {
        int row = sActive[t];
        unsigned long long n0 = 0ull, n1 = 0ull;
        if (t + 1 < cnt) {
            int nr = sActive[t + 1];
            n0 = g_mask[(size_t)nr * 64 + 2 * lane];
            n1 = g_mask[(size_t)nr * 64 + 2 * lane + 1];
        }
        int w = row >> 6;
        int owner = w >> 1;
        unsigned long long src = (w & 1) ? r1 : r0;
        unsigned long long v = __shfl_sync(0xffffffffu, src, owner);
        if (!((v >> (row & 63)) & 1ull)) {   // row is kept -> suppress its victims
            r0 |= m0;
            r1 |= m1;
        }
        m0 = n0; m1 = n1;
    }
    g_remv[2 * lane] = r0;
    g_remv[2 * lane + 1] = r1;
}

// ---------------- K8: final scores (out col 24) ----------------
__global__ void k_final(float* __restrict__ out) {
    int r = blockIdx.x * blockDim.x + threadIdx.x;
    if (r >= TOPK) return;
    bool removed = (g_remv[r >> 6] >> (r & 63)) & 1ull;
    out[(size_t)r * 25 + 24] = g_topk_val[r] * (removed ? 0.0f : 1.0f);
}

// ---------------- launch ----------------
extern "C" void kernel_launch(void* const* d_in, const int* in_sizes, int n_in,
                              void* d_out, int out_size) {
    const float* anchors = (const float*)d_in[0];
    const float* psm_v   = (const float*)d_in[1];
    const float* rm_v    = (const float*)d_in[2];
    const float* psm_i   = (const float*)d_in[3];
    const float* rm_i    = (const float*)d_in[4];
    const float* t_proj  = (const float*)d_in[5];
    const float* t_ego   = (const float*)d_in[6];
    float* out = (float*)d_out;

    cudaFuncSetAttribute(k_sort, cudaFuncAttributeMaxDynamicSharedMemorySize,
                         MAXCAND * (int)sizeof(unsigned long long));

    k_init<<<(NBUCKET + 255) / 256, 256>>>();
    k_scores<<<(NTOT + 255) / 256, 256>>>(psm_v, psm_i);
    k_findcut<<<1, 256>>>();
    k_compact<<<(NTOT + 255) / 256, 256>>>();
    k_sort<<<1, 1024, MAXCAND * sizeof(unsigned long long)>>>();
    k_decode<<<(TOPK + 127) / 128, 128>>>(anchors, rm_v, rm_i, t_proj, t_ego, out);
    k_mask<<<dim3(64, 64), 64>>>();
    k_nms<<<1, 32>>>();
    k_final<<<(TOPK + 255) / 256, 256>>>(out);
}

// round 4
// speedup vs baseline: 1.2655x; 1.2655x over previous
#include <cuda_runtime.h>
#include <math.h>

#define HH 256
#define WW 512
#define HW (HH*WW)            // 131072
#define NPB (HW*2)            // 262144 boxes per branch
#define NTOT (NPB*2)          // 524288 total
#define TOPK 4096
#define SCORE_THR 0.2f
#define NMS_THR 0.15f
#define NBUCKET 65536
#define MAXCAND 16384
#define RTILE 2048

// ---------------- scratch ----------------
__device__ float               g_scores[NTOT];
__device__ unsigned int        g_hist[NBUCKET];
__device__ int                 g_cut;
__device__ unsigned long long  g_cand[MAXCAND];
__device__ int                 g_cand_count;
__device__ float               g_topk_val[TOPK];
__device__ int                 g_topk_idx[TOPK];
__device__ float4              g_standup[TOPK];
__device__ unsigned long long  g_mask[TOPK * 64];   // 2MB suppression bitmask (upper-tri)
__device__ unsigned long long  g_any[64];
__device__ unsigned long long  g_remv[64];

// ---------------- K0: zero scratch ----------------
__global__ void k_init() {
    int i = blockIdx.x * blockDim.x + threadIdx.x;
    if (i < NBUCKET) g_hist[i] = 0u;
    if (i < 64)      g_any[i] = 0ull;
    if (i == 0)      g_cand_count = 0;
    if (i < TOPK)    { g_topk_val[i] = 0.0f; g_topk_idx[i] = 0; }
}

// ---------------- K1: sigmoid scores + bucket histogram ----------------
__global__ void k_scores(const float* __restrict__ psm_v, const float* __restrict__ psm_i) {
    int n = blockIdx.x * blockDim.x + threadIdx.x;
    if (n >= NTOT) return;
    int br = (n >= NPB);
    int m = br ? (n - NPB) : n;
    int cell = m >> 1, a = m & 1;
    float x = (br ? psm_i : psm_v)[a * HW + cell];
    float s = 1.0f / (1.0f + expf(-x));
    g_scores[n] = s;
    if (s > SCORE_THR) {
        unsigned int b = __float_as_uint(s) >> 16;
        atomicAdd(&g_hist[b], 1u);
    }
}

// ---------------- K2: find cut bucket ----------------
__global__ void k_findcut() {
    __shared__ unsigned int csum[256];
    int t = threadIdx.x;
    unsigned int sum = 0;
    int base = t * 256;
    for (int i = 0; i < 256; i++) sum += g_hist[base + i];
    csum[t] = sum;
    __syncthreads();
    if (t == 0) {
        unsigned int cum = 0;
        int c = 255;
        for (; c >= 0; c--) {
            if (cum + csum[c] >= TOPK) break;
            cum += csum[c];
        }
        if (c < 0) { g_cut = 0; return; }
        int b = c * 256 + 255;
        for (; b >= c * 256; b--) {
            cum += g_hist[b];
            if (cum >= TOPK) break;
        }
        if (b < c * 256) b = c * 256;
        g_cut = b;
    }
}

// ---------------- K3: compact candidates >= cut bucket ----------------
__global__ void k_compact() {
    int n = blockIdx.x * blockDim.x + threadIdx.x;
    if (n >= NTOT) return;
    float s = g_scores[n];
    if (s > SCORE_THR) {
        unsigned int bits = __float_as_uint(s);
        if ((int)(bits >> 16) >= g_cut) {
            int p = atomicAdd(&g_cand_count, 1);
            if (p < MAXCAND) {
                g_cand[p] = ((unsigned long long)bits << 32)
                          | (unsigned long long)(0xFFFFFFFFu - (unsigned int)n);
            }
        }
    }
}

// ---------------- K4: rank-by-count (replaces bitonic sort) ----------------
// keys unique (index embedded) -> rank = #{j: key_j > key_i} is a permutation.
__global__ void k_rank() {
    __shared__ unsigned long long tile[RTILE];
    int i = blockIdx.x * blockDim.x + threadIdx.x;
    int cnt = g_cand_count; if (cnt > MAXCAND) cnt = MAXCAND;
    unsigned long long myKey = (i < cnt) ? g_cand[i] : 0ull;
    int rank = 0;
    for (int base = 0; base < cnt; base += RTILE) {
        int m = cnt - base; if (m > RTILE) m = RTILE;
        for (int t = threadIdx.x; t < m; t += blockDim.x) tile[t] = g_cand[base + t];
        __syncthreads();
        int j = 0;
        for (; j + 8 <= m; j += 8) {
#pragma unroll
            for (int u = 0; u < 8; u++) rank += (tile[j + u] > myKey);
        }
        for (; j < m; j++) rank += (tile[j] > myKey);
        __syncthreads();
    }
    if (i < cnt && rank < TOPK) {
        g_topk_val[rank] = __uint_as_float((unsigned int)(myKey >> 32));
        g_topk_idx[rank] = (int)(0xFFFFFFFFu - (unsigned int)(myKey & 0xFFFFFFFFull));
    }
}

// ---------------- geometry helpers ----------------
__device__ __forceinline__ void make_corners(const float* b, float* cx, float* cy, float* cz) {
    const float sx[8] = { 0.5f, 0.5f,-0.5f,-0.5f, 0.5f, 0.5f,-0.5f,-0.5f};
    const float sy[8] = { 0.5f,-0.5f,-0.5f, 0.5f, 0.5f,-0.5f,-0.5f, 0.5f};
    const float sz[8] = {-0.5f,-0.5f,-0.5f,-0.5f, 0.5f, 0.5f, 0.5f, 0.5f};
    float c = cosf(b[6]), s = sinf(b[6]);
#pragma unroll
    for (int k = 0; k < 8; k++) {
        float x = b[5] * sx[k];
        float y = b[4] * sy[k];
        float z = b[3] * sz[k];
        cx[k] = x * c - y * s + b[0];
        cy[k] = x * s + y * c + b[1];
        cz[k] = z + b[2];
    }
}

__device__ __forceinline__ void apply_T(const float* __restrict__ T,
                                        float* cx, float* cy, float* cz) {
    float T00 = T[0], T01 = T[1], T02 = T[2],  T03 = T[3];
    float T10 = T[4], T11 = T[5], T12 = T[6],  T13 = T[7];
    float T20 = T[8], T21 = T[9], T22 = T[10], T23 = T[11];
#pragma unroll
    for (int k = 0; k < 8; k++) {
        float x = cx[k], y = cy[k], z = cz[k];
        cx[k] = T00 * x + T01 * y + T02 * z + T03;
        cy[k] = T10 * x + T11 * y + T12 * z + T13;
        cz[k] = T20 * x + T21 * y + T22 * z + T23;
    }
}

__device__ __forceinline__ void corner_to_center(const float* cx, const float* cy,
                                                 const float* cz, float* b) {
    float mx = 0.f, my = 0.f, mz = 0.f;
#pragma unroll
    for (int k = 0; k < 8; k++) { mx += cx[k]; my += cy[k]; mz += cz[k]; }
    mx *= 0.125f; my *= 0.125f; mz *= 0.125f;
    float h = (cz[4] + cz[5] + cz[6] + cz[7]) * 0.25f
            - (cz[0] + cz[1] + cz[2] + cz[3]) * 0.25f;
    const int li[4] = {0, 1, 4, 5}, lj[4] = {3, 2, 7, 6};
    const int wi[4] = {0, 3, 4, 7}, wj[4] = {1, 2, 5, 6};
    float l = 0.f, w = 0.f, sdx = 0.f, sdy = 0.f;
#pragma unroll
    for (int k = 0; k < 4; k++) {
        float dx = cx[li[k]] - cx[lj[k]];
        float dy = cy[li[k]] - cy[lj[k]];
        l += sqrtf(dx * dx + dy * dy);
        sdx += dx; sdy += dy;
    }
    l *= 0.25f;
#pragma unroll
    for (int k = 0; k < 4; k++) {
        float dx = cx[wi[k]] - cx[wj[k]];
        float dy = cy[wi[k]] - cy[wj[k]];
        w += sqrtf(dx * dx + dy * dy);
    }
    w *= 0.25f;
    float yaw = atan2f(sdy, sdx);
    b[0] = mx; b[1] = my; b[2] = mz; b[3] = h; b[4] = w; b[5] = l; b[6] = yaw;
}

// ---------------- K5: decode selected boxes ----------------
__global__ void k_decode(const float* __restrict__ anchors,
                         const float* __restrict__ rm_v,
                         const float* __restrict__ rm_i,
                         const float* __restrict__ t_proj,
                         const float* __restrict__ t_ego,
                         float* __restrict__ out) {
    int r = blockIdx.x * blockDim.x + threadIdx.x;
    if (r >= TOPK) return;
    int n = g_topk_idx[r];
    int br = (n >= NPB);
    int m = br ? (n - NPB) : n;
    const float* rm = br ? rm_i : rm_v;
    int cell = m >> 1, a = m & 1;
    const float* anc = anchors + (size_t)m * 7;

    float d[7];
#pragma unroll
    for (int j = 0; j < 7; j++) d[j] = rm[(a * 7 + j) * HW + cell];

    float a0 = anc[0], a1 = anc[1], a2 = anc[2], a3 = anc[3];
    float a4 = anc[4], a5 = anc[5], a6 = anc[6];
    float ad = sqrtf(a4 * a4 + a5 * a5);

    float b[7];
    b[0] = d[0] * ad + a0;
    b[1] = d[1] * ad + a1;
    b[2] = d[2] * a3 + a2;
    b[3] = expf(d[3]) * a3;
    b[4] = expf(d[4]) * a4;
    b[5] = expf(d[5]) * a5;
    b[6] = d[6] + a6;

    float cx[8], cy[8], cz[8];
    make_corners(b, cx, cy, cz);
    if (br) {
        apply_T(t_proj, cx, cy, cz);
        corner_to_center(cx, cy, cz, b);
        make_corners(b, cx, cy, cz);
    }
    apply_T(t_ego, cx, cy, cz);

    float mnx = cx[0], mny = cy[0], mxx = cx[0], mxy = cy[0];
    float* o = out + (size_t)r * 25;
#pragma unroll
    for (int k = 0; k < 8; k++) {
        o[k * 3 + 0] = cx[k];
        o[k * 3 + 1] = cy[k];
        o[k * 3 + 2] = cz[k];
        mnx = fminf(mnx, cx[k]); mny = fminf(mny, cy[k]);
        mxx = fmaxf(mxx, cx[k]); mxy = fmaxf(mxy, cy[k]);
    }
    g_standup[r] = make_float4(mnx, mny, mxx, mxy);
}

// ---------------- K6: suppression bitmask matrix (upper triangle only) ----------------
__global__ void k_mask() {
    __shared__ float4 cb[64];
    int t = threadIdx.x;                 // 64 threads
    int bx = blockIdx.x, by = blockIdx.y;
    int row = by * 64 + t;
    if (bx < by) {                       // strictly below diagonal: all-zero
        g_mask[(size_t)row * 64 + bx] = 0ull;
        return;
    }
    int col0 = bx * 64;
    cb[t] = g_standup[col0 + t];
    __syncthreads();
    float4 rb = g_standup[row];
    float rArea = (rb.z - rb.x) * (rb.w - rb.y);
    unsigned long long bits = 0ull;
#pragma unroll 4
    for (int j = 0; j < 64; j++) {
        int col = col0 + j;
        if (col > row) {
            float4 c = cb[j];
            float lx = fmaxf(rb.x, c.x), ly = fmaxf(rb.y, c.y);
            float rx = fminf(rb.z, c.z), ry = fminf(rb.w, c.w);
            float w = fmaxf(rx - lx, 0.f), h = fmaxf(ry - ly, 0.f);
            float inter = w * h;
            float cArea = (c.z - c.x) * (c.w - c.y);
            float iou = inter / (rArea + cArea - inter + 1e-6f);
            if (iou > NMS_THR) bits |= (1ull << j);
        }
    }
    g_mask[(size_t)row * 64 + bx] = bits;
    if (bits) atomicOr(&g_any[row >> 6], 1ull << (row & 63));
}

// spread 32 bits of x to the even bit positions of a 64-bit word
__device__ __forceinline__ unsigned long long expand_even(unsigned int x) {
    unsigned long long v = x;
    v = (v | (v << 16)) & 0x0000FFFF0000FFFFull;
    v = (v | (v << 8))  & 0x00FF00FF00FF00FFull;
    v = (v | (v << 4))  & 0x0F0F0F0F0F0F0F0Full;
    v = (v | (v << 2))  & 0x3333333333333333ull;
    v = (v | (v << 1))  & 0x5555555555555555ull;
    return v;
}

// ---------------- K7: blocked greedy NMS (diagonal serial + parallel cross) ----------------
// Single warp. Lane L owns remv words 2L, 2L+1.
// Per 64-row word w: (a) all lanes redundantly run the serial scan of the
// diagonal 64x64 block (smem-staged, nonzero-row bitmap skips no-op rows;
// row order independent of the rw chain), (b) kept rows' cross-word masks are
// OR-applied in parallel (independent LDG.128, order among kept rows commutes).
__global__ void k_nms() {
    int lane = threadIdx.x;              // 32
    __shared__ unsigned long long diag[2][64];
    __shared__ unsigned long long s_any[64];
    __shared__ unsigned long long s_nz[2];

    s_any[2 * lane]     = g_any[2 * lane];
    s_any[2 * lane + 1] = g_any[2 * lane + 1];

    // init removed = !valid
    unsigned long long r0 = 0ull, r1 = 0ull;
    {
        int rowA = (2 * lane) << 6, rowB = (2 * lane + 1) << 6;
#pragma unroll 8
        for (int bb = 0; bb < 64; bb++) {
            r0 |= (g_topk_val[rowA + bb] > SCORE_THR) ? 0ull : (1ull << bb);
            r1 |= (g_topk_val[rowB + bb] > SCORE_THR) ? 0ull : (1ull << bb);
        }
    }

    // prefetch diag block for w=0
    {
        unsigned long long d0 = g_mask[((size_t)(2 * lane)) * 64 + 0];
        unsigned long long d1 = g_mask[((size_t)(2 * lane + 1)) * 64 + 0];
        diag[0][2 * lane] = d0; diag[0][2 * lane + 1] = d1;
        unsigned int be = __ballot_sync(0xffffffffu, d0 != 0ull);
        unsigned int bo = __ballot_sync(0xffffffffu, d1 != 0ull);
        if (lane == 0) s_nz[0] = expand_even(be) | (expand_even(bo) << 1);
    }
    __syncwarp();

    for (int w = 0; w < 64; w++) {
        int cur = w & 1, nxt = cur ^ 1;
        // issue next diag loads early (latency hidden behind this word's work)
        unsigned long long nd0 = 0ull, nd1 = 0ull;
        if (w + 1 < 64) {
            size_t base = (size_t)(w + 1) * 64;
            nd0 = g_mask[(base + 2 * lane)     * 64 + (w + 1)];
            nd1 = g_mask[(base + 2 * lane + 1) * 64 + (w + 1)];
        }
        int owner = w >> 1;
        unsigned long long rw =
            __shfl_sync(0xffffffffu, (w & 1) ? r1 : r0, owner);

        // (a) serial diagonal scan — all lanes compute identically
        unsigned long long it = s_nz[cur] & ~rw;
        while (it) {
            int b = __ffsll((long long)it) - 1;
            it &= it - 1;
            unsigned long long m = diag[cur][b];
            rw |= ((rw >> b) & 1ull) ? 0ull : m;
        }
        if (lane == owner) { if (w & 1) r1 = rw; else r0 = rw; }

        // (b) parallel cross suppression by kept rows of this word
        unsigned long long ka = s_any[w] & ~rw;
        while (ka) {
            int b = __ffsll((long long)ka) - 1;
            ka &= ka - 1;
            size_t row = (size_t)w * 64 + b;
            ulonglong2 mm = *reinterpret_cast<const ulonglong2*>(
                &g_mask[row * 64 + 2 * lane]);
            r0 |= mm.x; r1 |= mm.y;
        }

        // commit next diag block
        if (w + 1 < 64) {
            diag[nxt][2 * lane] = nd0; diag[nxt][2 * lane + 1] = nd1;
            unsigned int be = __ballot_sync(0xffffffffu, nd0 != 0ull);
            unsigned int bo = __ballot_sync(0xffffffffu, nd1 != 0ull);
            if (lane == 0) s_nz[nxt] = expand_even(be) | (expand_even(bo) << 1);
        }
        __syncwarp();
    }
    g_remv[2 * lane]     = r0;
    g_remv[2 * lane + 1] = r1;
}

// ---------------- K8: final scores ----------------
__global__ void k_final(float* __restrict__ out) {
    int r = blockIdx.x * blockDim.x + threadIdx.x;
    if (r >= TOPK) return;
    bool removed = (g_remv[r >> 6] >> (r & 63)) & 1ull;
    out[(size_t)r * 25 + 24] = g_topk_val[r] * (removed ? 0.0f : 1.0f);
}

// ---------------- launch ----------------
extern "C" void kernel_launch(void* const* d_in, const int* in_sizes, int n_in,
                              void* d_out, int out_size) {
    const float* anchors = (const float*)d_in[0];
    const float* psm_v   = (const float*)d_in[1];
    const float* rm_v    = (const float*)d_in[2];
    const float* psm_i   = (const float*)d_in[3];
    const float* rm_i    = (const float*)d_in[4];
    const float* t_proj  = (const float*)d_in[5];
    const float* t_ego   = (const float*)d_in[6];
    float* out = (float*)d_out;

    k_init<<<256, 256>>>();
    k_scores<<<(NTOT + 255) / 256, 256>>>(psm_v, psm_i);
    k_findcut<<<1, 256>>>();
    k_compact<<<(NTOT + 255) / 256, 256>>>();
    k_rank<<<MAXCAND / 128, 128>>>();
    k_decode<<<(TOPK + 127) / 128, 128>>>(anchors, rm_v, rm_i, t_proj, t_ego, out);
    k_mask<<<dim3(64, 64), 64>>>();
    k_nms<<<1, 32>>>();
    k_final<<<(TOPK + 255) / 256, 256>>>(out);
}

// round 5
// speedup vs baseline: 3.0727x; 2.4281x over previous
#include <cuda_runtime.h>
#include <math.h>

#define HH 256
#define WW 512
#define HW (HH*WW)            // 131072
#define NPB (HW*2)            // 262144 boxes per branch
#define NTOT (NPB*2)          // 524288 total
#define TOPK 4096
#define SCORE_THR 0.2f
#define NMS_THR 0.15f
#define NBUCKET 65536
#define MAXCAND 16384
#define RTILE 2048

// ---------------- scratch ----------------
__device__ unsigned int        g_hist[NBUCKET];
__device__ unsigned int        g_csum[256];
__device__ int                 g_cut;
__device__ unsigned long long  g_cand[MAXCAND];
__device__ int                 g_cand_count;
__device__ float               g_topk_val[TOPK];
__device__ int                 g_topk_idx[TOPK];
__device__ float4              g_standup[TOPK];
__device__ unsigned long long  g_mask[TOPK * 64];   // upper-tri suppression bitmask
__device__ unsigned long long  g_remv[64];

__device__ __forceinline__ float sigmoid_ref(float x) {
    return 1.0f / (1.0f + expf(-x));
}

// ---------------- K0: zero scratch ----------------
__global__ void k_init() {
    int i = blockIdx.x * blockDim.x + threadIdx.x;
    if (i < NBUCKET) g_hist[i] = 0u;
    if (i == 0)      g_cand_count = 0;
    if (i < TOPK)    { g_topk_val[i] = 0.0f; g_topk_idx[i] = 0; }
}

// ---------------- K1: sigmoid scores -> bucket histogram ----------------
__global__ void k_scores(const float* __restrict__ psm_v, const float* __restrict__ psm_i) {
    int n = blockIdx.x * blockDim.x + threadIdx.x;
    if (n >= NTOT) return;
    int br = (n >= NPB);
    int m = br ? (n - NPB) : n;
    int cell = m >> 1, a = m & 1;
    float x = (br ? psm_i : psm_v)[a * HW + cell];
    float s = sigmoid_ref(x);
    if (s > SCORE_THR) {
        unsigned int b = __float_as_uint(s) >> 16;
        atomicAdd(&g_hist[b], 1u);
    }
}

// ---------------- K1b: coarse 256-bucket sums (parallel) ----------------
__global__ void k_coarse() {
    __shared__ unsigned int red[256];
    int c = blockIdx.x, t = threadIdx.x;
    red[t] = g_hist[c * 256 + t];
    __syncthreads();
    for (int s = 128; s > 0; s >>= 1) {
        if (t < s) red[t] += red[t + s];
        __syncthreads();
    }
    if (t == 0) g_csum[c] = red[0];
}

// ---------------- K2: find cut bucket (smem-staged scans) ----------------
__global__ void k_findcut() {
    __shared__ unsigned int s_c[256];
    __shared__ int s_coarse;
    __shared__ unsigned int s_cumabove;
    int t = threadIdx.x;
    s_c[t] = g_csum[t];
    __syncthreads();
    if (t == 0) {
        unsigned int cum = 0;
        int c = 255;
        for (; c >= 0; c--) {
            if (cum + s_c[c] >= TOPK) break;
            cum += s_c[c];
        }
        s_coarse = c; s_cumabove = cum;
    }
    __syncthreads();
    int c = s_coarse;
    if (c < 0) { if (t == 0) g_cut = 0; return; }
    s_c[t] = g_hist[c * 256 + t];
    __syncthreads();
    if (t == 0) {
        unsigned int cum = s_cumabove;
        int b = 255;
        for (; b >= 0; b--) {
            cum += s_c[b];
            if (cum >= TOPK) break;
        }
        if (b < 0) b = 0;
        g_cut = c * 256 + b;
    }
}

// ---------------- K3: compact candidates >= cut (recompute sigmoid) ----------------
__global__ void k_compact(const float* __restrict__ psm_v, const float* __restrict__ psm_i) {
    int n = blockIdx.x * blockDim.x + threadIdx.x;
    if (n >= NTOT) return;
    int br = (n >= NPB);
    int m = br ? (n - NPB) : n;
    int cell = m >> 1, a = m & 1;
    float x = (br ? psm_i : psm_v)[a * HW + cell];
    float s = sigmoid_ref(x);
    if (s > SCORE_THR) {
        unsigned int bits = __float_as_uint(s);
        if ((int)(bits >> 16) >= g_cut) {
            int p = atomicAdd(&g_cand_count, 1);
            if (p < MAXCAND) {
                g_cand[p] = ((unsigned long long)bits << 32)
                          | (unsigned long long)(0xFFFFFFFFu - (unsigned int)n);
            }
        }
    }
}

// ---------------- K4: rank-by-count ----------------
__global__ void k_rank() {
    __shared__ unsigned long long tile[RTILE];
    int cnt = g_cand_count; if (cnt > MAXCAND) cnt = MAXCAND;
    if ((int)(blockIdx.x * blockDim.x) >= cnt) return;   // uniform early-exit
    int i = blockIdx.x * blockDim.x + threadIdx.x;
    unsigned long long myKey = (i < cnt) ? g_cand[i] : 0ull;
    int rank = 0;
    for (int base = 0; base < cnt; base += RTILE) {
        int m = cnt - base; if (m > RTILE) m = RTILE;
        for (int t = threadIdx.x; t < m; t += blockDim.x) tile[t] = g_cand[base + t];
        __syncthreads();
        int j = 0;
        for (; j + 8 <= m; j += 8) {
#pragma unroll
            for (int u = 0; u < 8; u++) rank += (tile[j + u] > myKey);
        }
        for (; j < m; j++) rank += (tile[j] > myKey);
        __syncthreads();
    }
    if (i < cnt && rank < TOPK) {
        g_topk_val[rank] = __uint_as_float((unsigned int)(myKey >> 32));
        g_topk_idx[rank] = (int)(0xFFFFFFFFu - (unsigned int)(myKey & 0xFFFFFFFFull));
    }
}

// ---------------- geometry helpers ----------------
__device__ __forceinline__ void make_corners(const float* b, float* cx, float* cy, float* cz) {
    const float sx[8] = { 0.5f, 0.5f,-0.5f,-0.5f, 0.5f, 0.5f,-0.5f,-0.5f};
    const float sy[8] = { 0.5f,-0.5f,-0.5f, 0.5f, 0.5f,-0.5f,-0.5f, 0.5f};
    const float sz[8] = {-0.5f,-0.5f,-0.5f,-0.5f, 0.5f, 0.5f, 0.5f, 0.5f};
    float c = cosf(b[6]), s = sinf(b[6]);
#pragma unroll
    for (int k = 0; k < 8; k++) {
        float x = b[5] * sx[k];
        float y = b[4] * sy[k];
        float z = b[3] * sz[k];
        cx[k] = x * c - y * s + b[0];
        cy[k] = x * s + y * c + b[1];
        cz[k] = z + b[2];
    }
}

__device__ __forceinline__ void apply_T(const float* __restrict__ T,
                                        float* cx, float* cy, float* cz) {
    float T00 = T[0], T01 = T[1], T02 = T[2],  T03 = T[3];
    float T10 = T[4], T11 = T[5], T12 = T[6],  T13 = T[7];
    float T20 = T[8], T21 = T[9], T22 = T[10], T23 = T[11];
#pragma unroll
    for (int k = 0; k < 8; k++) {
        float x = cx[k], y = cy[k], z = cz[k];
        cx[k] = T00 * x + T01 * y + T02 * z + T03;
        cy[k] = T10 * x + T11 * y + T12 * z + T13;
        cz[k] = T20 * x + T21 * y + T22 * z + T23;
    }
}

__device__ __forceinline__ void corner_to_center(const float* cx, const float* cy,
                                                 const float* cz, float* b) {
    float mx = 0.f, my = 0.f, mz = 0.f;
#pragma unroll
    for (int k = 0; k < 8; k++) { mx += cx[k]; my += cy[k]; mz += cz[k]; }
    mx *= 0.125f; my *= 0.125f; mz *= 0.125f;
    float h = (cz[4] + cz[5] + cz[6] + cz[7]) * 0.25f
            - (cz[0] + cz[1] + cz[2] + cz[3]) * 0.25f;
    const int li[4] = {0, 1, 4, 5}, lj[4] = {3, 2, 7, 6};
    const int wi[4] = {0, 3, 4, 7}, wj[4] = {1, 2, 5, 6};
    float l = 0.f, w = 0.f, sdx = 0.f, sdy = 0.f;
#pragma unroll
    for (int k = 0; k < 4; k++) {
        float dx = cx[li[k]] - cx[lj[k]];
        float dy = cy[li[k]] - cy[lj[k]];
        l += sqrtf(dx * dx + dy * dy);
        sdx += dx; sdy += dy;
    }
    l *= 0.25f;
#pragma unroll
    for (int k = 0; k < 4; k++) {
        float dx = cx[wi[k]] - cx[wj[k]];
        float dy = cy[wi[k]] - cy[wj[k]];
        w += sqrtf(dx * dx + dy * dy);
    }
    w *= 0.25f;
    float yaw = atan2f(sdy, sdx);
    b[0] = mx; b[1] = my; b[2] = mz; b[3] = h; b[4] = w; b[5] = l; b[6] = yaw;
}

// ---------------- K5: decode selected boxes ----------------
__global__ void k_decode(const float* __restrict__ anchors,
                         const float* __restrict__ rm_v,
                         const float* __restrict__ rm_i,
                         const float* __restrict__ t_proj,
                         const float* __restrict__ t_ego,
                         float* __restrict__ out) {
    int r = blockIdx.x * blockDim.x + threadIdx.x;
    if (r >= TOPK) return;
    int n = g_topk_idx[r];
    int br = (n >= NPB);
    int m = br ? (n - NPB) : n;
    const float* rm = br ? rm_i : rm_v;
    int cell = m >> 1, a = m & 1;
    const float* anc = anchors + (size_t)m * 7;

    float d[7];
#pragma unroll
    for (int j = 0; j < 7; j++) d[j] = rm[(a * 7 + j) * HW + cell];

    float a0 = anc[0], a1 = anc[1], a2 = anc[2], a3 = anc[3];
    float a4 = anc[4], a5 = anc[5], a6 = anc[6];
    float ad = sqrtf(a4 * a4 + a5 * a5);

    float b[7];
    b[0] = d[0] * ad + a0;
    b[1] = d[1] * ad + a1;
    b[2] = d[2] * a3 + a2;
    b[3] = expf(d[3]) * a3;
    b[4] = expf(d[4]) * a4;
    b[5] = expf(d[5]) * a5;
    b[6] = d[6] + a6;

    float cx[8], cy[8], cz[8];
    make_corners(b, cx, cy, cz);
    if (br) {
        apply_T(t_proj, cx, cy, cz);
        corner_to_center(cx, cy, cz, b);
        make_corners(b, cx, cy, cz);
    }
    apply_T(t_ego, cx, cy, cz);

    float mnx = cx[0], mny = cy[0], mxx = cx[0], mxy = cy[0];
    float* o = out + (size_t)r * 25;
#pragma unroll
    for (int k = 0; k < 8; k++) {
        o[k * 3 + 0] = cx[k];
        o[k * 3 + 1] = cy[k];
        o[k * 3 + 2] = cz[k];
        mnx = fminf(mnx, cx[k]); mny = fminf(mny, cy[k]);
        mxx = fmaxf(mxx, cx[k]); mxy = fmaxf(mxy, cy[k]);
    }
    g_standup[r] = make_float4(mnx, mny, mxx, mxy);
}

// ---------------- K6: suppression bitmask matrix (upper triangle only) ----------------
__global__ void k_mask() {
    __shared__ float4 cb[64];
    int t = threadIdx.x;                 // 64 threads
    int bx = blockIdx.x, by = blockIdx.y;
    if (bx < by) return;                 // lower triangle never read
    int row = by * 64 + t;
    int col0 = bx * 64;
    cb[t] = g_standup[col0 + t];
    __syncthreads();
    float4 rb = g_standup[row];
    float rArea = (rb.z - rb.x) * (rb.w - rb.y);
    unsigned long long bits = 0ull;
#pragma unroll 4
    for (int j = 0; j < 64; j++) {
        int col = col0 + j;
        if (col > row) {
            float4 c = cb[j];
            float lx = fmaxf(rb.x, c.x), ly = fmaxf(rb.y, c.y);
            float rx = fminf(rb.z, c.z), ry = fminf(rb.w, c.w);
            float w = fmaxf(rx - lx, 0.f), h = fmaxf(ry - ly, 0.f);
            float inter = w * h;
            float cArea = (c.z - c.x) * (c.w - c.y);
            float iou = inter / (rArea + cArea - inter + 1e-6f);
            if (iou > NMS_THR) bits |= (1ull << j);
        }
    }
    g_mask[(size_t)row * 64 + bx] = bits;
}

// ---------------- K7: cooperative blocked greedy NMS ----------------
// 1024 threads. Double-buffered smem holds all 64 mask rows of the current
// 64-rank word (transposed: buf[word j][row b]). Per word: serial diagonal
// chain by thread 0 (register/smem ALU chain only), then parallel OR-reduce
// pushes kept rows' suppression into all future words' remv. Next word's rows
// prefetched concurrently.
#define NMS_BUF(s, j, b) sm[(((s) * 64 + (j)) * 65) + (b)]
__global__ void k_nms() {
    extern __shared__ unsigned long long sm[];       // 2*64*65 entries
    __shared__ unsigned long long s_remv[64];
    int tid = threadIdx.x;
    int lane = tid & 31, wid = tid >> 5;

    // init removed = !valid (warp ballots, 32 consecutive ranks each)
#pragma unroll
    for (int it = 0; it < 4; it++) {
        int r = it * 1024 + tid;
        float v = g_topk_val[r];
        unsigned int ball = __ballot_sync(0xffffffffu, !(v > SCORE_THR));
        if (lane == 0) ((unsigned int*)s_remv)[r >> 5] = ball;
    }

    // prefetch word 0 rows
    int prow = tid >> 4;                 // 0..63
    int pcol = (tid & 15) * 4;           // 0..60 step 4
    {
        const unsigned long long* g = &g_mask[((size_t)prow) * 64 + pcol];
        ulonglong2 A = *(const ulonglong2*)g;
        ulonglong2 B = *(const ulonglong2*)(g + 2);
        NMS_BUF(0, pcol + 0, prow) = A.x;
        NMS_BUF(0, pcol + 1, prow) = A.y;
        NMS_BUF(0, pcol + 2, prow) = B.x;
        NMS_BUF(0, pcol + 3, prow) = B.y;
    }
    __syncthreads();

    for (int w = 0; w < 64; w++) {
        int cur = w & 1, nxt = cur ^ 1;
        bool pf = (w < 63);
        ulonglong2 A, B;
        if (pf) {
            const unsigned long long* g =
                &g_mask[((size_t)(w + 1) * 64 + prow) * 64 + pcol];
            A = *(const ulonglong2*)g;
            B = *(const ulonglong2*)(g + 2);
        }

        // serial diagonal greedy chain (thread 0)
        if (tid == 0) {
            unsigned long long rw = s_remv[w];
#pragma unroll
            for (int b = 0; b < 64; b++) {
                unsigned long long m = NMS_BUF(cur, w, b);
                rw |= ((rw >> b) & 1ull) ? 0ull : m;
            }
            s_remv[w] = rw;
        }
        __syncthreads();

        // parallel cross suppression: word j gets OR of kept rows' masks
        unsigned long long kept = ~s_remv[w];
#pragma unroll
        for (int half = 0; half < 2; half++) {
            int j = w + 1 + wid + half * 32;
            if (j < 64) {
                unsigned long long acc = 0ull;
                int b0 = lane, b1 = lane + 32;
                if ((kept >> b0) & 1ull) acc |= NMS_BUF(cur, j, b0);
                if ((kept >> b1) & 1ull) acc |= NMS_BUF(cur, j, b1);
                unsigned int lo = (unsigned int)acc;
                unsigned int hi = (unsigned int)(acc >> 32);
                lo = __reduce_or_sync(0xffffffffu, lo);
                hi = __reduce_or_sync(0xffffffffu, hi);
                if (lane == 0)
                    s_remv[j] |= ((unsigned long long)hi << 32) | lo;
            }
        }
        __syncthreads();

        if (pf) {
            NMS_BUF(nxt, pcol + 0, prow) = A.x;
            NMS_BUF(nxt, pcol + 1, prow) = A.y;
            NMS_BUF(nxt, pcol + 2, prow) = B.x;
            NMS_BUF(nxt, pcol + 3, prow) = B.y;
        }
        __syncthreads();
    }

    if (tid < 64) g_remv[tid] = s_remv[tid];
}

// ---------------- K8: final scores ----------------
__global__ void k_final(float* __restrict__ out) {
    int r = blockIdx.x * blockDim.x + threadIdx.x;
    if (r >= TOPK) return;
    bool removed = (g_remv[r >> 6] >> (r & 63)) & 1ull;
    out[(size_t)r * 25 + 24] = g_topk_val[r] * (removed ? 0.0f : 1.0f);
}

// ---------------- launch ----------------
extern "C" void kernel_launch(void* const* d_in, const int* in_sizes, int n_in,
                              void* d_out, int out_size) {
    const float* anchors = (const float*)d_in[0];
    const float* psm_v   = (const float*)d_in[1];
    const float* rm_v    = (const float*)d_in[2];
    const float* psm_i   = (const float*)d_in[3];
    const float* rm_i    = (const float*)d_in[4];
    const float* t_proj  = (const float*)d_in[5];
    const float* t_ego   = (const float*)d_in[6];
    float* out = (float*)d_out;

    static int s_attr_done = 0;
    if (!s_attr_done) {
        cudaFuncSetAttribute(k_nms, cudaFuncAttributeMaxDynamicSharedMemorySize,
                             2 * 64 * 65 * (int)sizeof(unsigned long long));
        s_attr_done = 1;
    }

    k_init<<<256, 256>>>();
    k_scores<<<(NTOT + 255) / 256, 256>>>(psm_v, psm_i);
    k_coarse<<<256, 256>>>();
    k_findcut<<<1, 256>>>();
    k_compact<<<(NTOT + 255) / 256, 256>>>(psm_v, psm_i);
    k_rank<<<MAXCAND / 128, 128>>>();
    k_decode<<<(TOPK + 127) / 128, 128>>>(anchors, rm_v, rm_i, t_proj, t_ego, out);
    k_mask<<<dim3(64, 64), 64>>>();
    k_nms<<<1, 1024, 2 * 64 * 65 * sizeof(unsigned long long)>>>();
    k_final<<<(TOPK + 255) / 256, 256>>>(out);
}